// round 16
// baseline (speedup 1.0000x reference)
#include <cuda_runtime.h>
#include <cuda_bf16.h>
#include <math.h>

#define GRID 128
#define TPB  256
#define Bp   512
#define Dd   64
#define Cc   512
#define NBs  8
#define MC   8
#define NBINS 32768
#define BIN_SC ((float)NBINS/64.0f)
#define BPAD 16

__device__ __nv_bfloat16 g_hA[Bp*Cc];
__device__ __nv_bfloat16 g_hB[Bp*Cc];
__device__ float g_osp[16*Bp*Dd];     // out-layer partials per n-tile
__device__ float g_d2[Bp*Bp];
__device__ float g_temb[NBs*2*Cc];
__device__ float g_tg1[NBs*Cc];
__device__ float g_bias1[NBs*Cc];
__device__ float g_betas[NBs+1];
__device__ __align__(16) int g_hist[2][NBINS];
__device__ unsigned long long g_flags[GRID*BPAD];
__device__ unsigned long long g_epoch = 0ULL;
// weights transposed to [n][k] and converted to bf16 at setup
__device__ __nv_bfloat16 g_WinT[Cc*Dd];      // [n=Cc][k=Dd]
__device__ __nv_bfloat16 g_WhT[3*Cc*Cc];     // [l][n][k]
__device__ __nv_bfloat16 g_WoutT[Dd*Cc];     // [d][k]

#define SA 72    // A smem half-stride (conflict-free frags)
#define SW 520   // resident W half-stride (bank = lane, conflict-free)
#define SX 520   // P6 X/A stride

struct SmG2 {
    __nv_bfloat16 A[2][3][64*SA];   // [gid][stage]
    float redf[64*33];
    __nv_bfloat16 redh[64*SA];
};
struct SmP { float Xi[32*64]; float Xj[64*64]; };
struct SmU {
    __nv_bfloat16 Xt[64*SX];
    __nv_bfloat16 Aw[16*SX];
    float T[4*64];
    float S[4];
    float wm[4][MC];
};
struct SmM { int cnt[8]; int woff[8]; float v[2]; };
struct SmAll {
    __nv_bfloat16 Wh[3][32*SW];     // resident hidden-layer W tiles (this block's n0)
    __nv_bfloat16 Win[32*SA];       // resident input-layer W tile
    __align__(16) union { SmG2 g; SmP p; SmU u; SmM m; } un;
};

__device__ __forceinline__ float gelu_t(float x){
    float x3 = x*x*x;
    return 0.5f*x*(1.0f+tanhf(0.7978845608028654f*(x+0.044715f*x3)));
}

__device__ __forceinline__ unsigned bf2(float lo, float hi){
    unsigned r;
    asm("cvt.rn.bf16x2.f32 %0, %1, %2;" : "=r"(r) : "f"(hi), "f"(lo));
    return r;
}

__device__ __forceinline__ void mma_bf16(float* acc,
    unsigned a0, unsigned a1, unsigned a2, unsigned a3,
    unsigned b0, unsigned b1)
{
    asm volatile(
        "mma.sync.aligned.m16n8k16.row.col.f32.bf16.bf16.f32 "
        "{%0,%1,%2,%3}, {%4,%5,%6,%7}, {%8,%9}, {%0,%1,%2,%3};"
        : "+f"(acc[0]), "+f"(acc[1]), "+f"(acc[2]), "+f"(acc[3])
        : "r"(a0), "r"(a1), "r"(a2), "r"(a3), "r"(b0), "r"(b1));
}

__device__ __forceinline__ void cpa16(void* s, const void* g){
    unsigned sa = (unsigned)__cvta_generic_to_shared(s);
    asm volatile("cp.async.cg.shared.global [%0], [%1], 16;" :: "r"(sa), "l"(g));
}
#define CPA_COMMIT() asm volatile("cp.async.commit_group;" ::: "memory")

// L2-direct loads (bypass L1) for cross-phase re-read data
__device__ __forceinline__ float4 ldcg4(const float* p){
    float4 v;
    asm volatile("ld.global.cg.v4.f32 {%0,%1,%2,%3}, [%4];"
                 : "=f"(v.x),"=f"(v.y),"=f"(v.z),"=f"(v.w) : "l"(p));
    return v;
}
__device__ __forceinline__ float ldcg1(const float* p){
    float v;
    asm volatile("ld.global.cg.f32 %0, [%1];" : "=f"(v) : "l"(p));
    return v;
}
__device__ __forceinline__ int4 ldcg4i(const int* p){
    int4 v;
    asm volatile("ld.global.cg.v4.s32 {%0,%1,%2,%3}, [%4];"
                 : "=r"(v.x),"=r"(v.y),"=r"(v.z),"=r"(v.w) : "l"(p));
    return v;
}

__device__ __forceinline__ unsigned long long ld_acq(const unsigned long long* p){
    unsigned long long v;
    asm volatile("ld.acquire.gpu.global.u64 %0, [%1];" : "=l"(v) : "l"(p) : "memory");
    return v;
}
__device__ __forceinline__ void st_rel(unsigned long long* p, unsigned long long v){
    asm volatile("st.release.gpu.global.u64 [%0], %1;" :: "l"(p), "l"(v) : "memory");
}

// relay barrier, minimal poll traffic:
//   non-zero blocks: tid0 writes own flag (release), tid0 polls epoch (acquire)
//   block 0: 127 threads each poll one flag, then tid0 publishes epoch
__device__ __forceinline__ void gridbar3(int blk, int tid, unsigned long long target){
    __syncthreads();
    if (blk == 0){
        if (tid > 0 && tid < GRID){
            while (ld_acq(&g_flags[tid*BPAD]) < target) { }
        }
        __syncthreads();
        if (tid == 0) st_rel(&g_epoch, target);
    } else {
        if (tid == 0){
            st_rel(&g_flags[blk*BPAD], target);
            while (ld_acq(&g_epoch) < target) { }
        }
        __syncthreads();
    }
}

#define GB() do { ecnt++; gridbar3(blk, tid, ebase + ecnt); } while(0)

// one 64x32 output tile of C = act(A@W + bias) via bf16 tensor cores.
// 256 threads, 2-way K-split. W read from RESIDENT smem (stride Wstr).
// K=512: A-only cp.async 3-stage ring, 64-half chunks. K=64 (convA): reg conv.
__device__ __forceinline__ void gemm_bf16(
    const void* Aptr, int Astr, int convA,
    const __nv_bfloat16* __restrict__ Wres, int Wstr,
    int m0, int klen,
    const float* __restrict__ bias, int n0, int act,
    int fold, float* __restrict__ fold_out,
    __nv_bfloat16* __restrict__ C, int Cstr, SmAll* sm)
{
    int tid  = threadIdx.x;
    int gid  = tid >> 7;
    int tg   = tid & 127;
    int warp = tg >> 5, lane = tid & 31;
    int g = lane >> 2, t = lane & 3;

    float acc[4][4] = {};

    if (convA){
        // single 32-half chunk per gid (P1: fp32 x converted to bf16)
        int kb0 = gid*32;
        int arow = tg >> 1, kseg = (tg & 1)*16;
        const float* Af = (const float*)Aptr;
        const float* ap = &Af[(size_t)(m0+arow)*Astr + kb0 + kseg];
        float4 f0 = ldcg4(ap),   f1 = ldcg4(ap+4);
        float4 f2 = ldcg4(ap+8), f3 = ldcg4(ap+12);
        uint4 ua, ub;
        ua.x = bf2(f0.x,f0.y); ua.y = bf2(f0.z,f0.w);
        ua.z = bf2(f1.x,f1.y); ua.w = bf2(f1.z,f1.w);
        ub.x = bf2(f2.x,f2.y); ub.y = bf2(f2.z,f2.w);
        ub.z = bf2(f3.x,f3.y); ub.w = bf2(f3.z,f3.w);
        __nv_bfloat16* As = sm->un.g.A[gid][0];
        *(uint4*)&As[arow*SA + kseg]     = ua;
        *(uint4*)&As[arow*SA + kseg + 8] = ub;
        __syncthreads();
        #pragma unroll
        for (int kk = 0; kk < 2; kk++){
            int ab = (16*warp + g)*SA + kk*16 + 2*t;
            unsigned a0 = *(const unsigned*)&As[ab];
            unsigned a1 = *(const unsigned*)&As[ab + 8*SA];
            unsigned a2 = *(const unsigned*)&As[ab + 8];
            unsigned a3 = *(const unsigned*)&As[ab + 8*SA + 8];
            #pragma unroll
            for (int c4 = 0; c4 < 4; c4++){
                int bb = (c4*8 + g)*Wstr + kb0 + kk*16 + 2*t;
                unsigned b0 = *(const unsigned*)&Wres[bb];
                unsigned b1 = *(const unsigned*)&Wres[bb + 8];
                mma_bf16(acc[c4], a0, a1, a2, a3, b0, b1);
            }
        }
    } else {
        // K=512: 4 chunks of 64 halves per gid, A-only 3-stage cp.async ring
        const __nv_bfloat16* Ah = (const __nv_bfloat16*)Aptr;
        int kb0 = gid*256;
        #define STAGE64(chunk, st) do {                                           \
            int kb_ = kb0 + (chunk)*64;                                           \
            __nv_bfloat16* As_ = sm->un.g.A[gid][st];                             \
            _Pragma("unroll")                                                     \
            for (int q = 0; q < 4; q++){                                          \
                int u = tg + q*128;                                               \
                cpa16(&As_[(u>>3)*SA + (u&7)*8],                                  \
                      &Ah[(size_t)(m0+(u>>3))*Astr + kb_ + (u&7)*8]);             \
            }                                                                     \
            CPA_COMMIT();                                                         \
        } while(0)

        STAGE64(0, 0);
        STAGE64(1, 1);
        #pragma unroll
        for (int c = 0; c < 4; c++){
            if (c < 3) asm volatile("cp.async.wait_group 1;" ::: "memory");
            else       asm volatile("cp.async.wait_group 0;" ::: "memory");
            __syncthreads();
            if (c+2 < 4) STAGE64(c+2, (c+2)%3);
            const __nv_bfloat16* As = sm->un.g.A[gid][c%3];
            int wbase = kb0 + c*64;
            #pragma unroll
            for (int kk = 0; kk < 4; kk++){
                int ab = (16*warp + g)*SA + kk*16 + 2*t;
                unsigned a0 = *(const unsigned*)&As[ab];
                unsigned a1 = *(const unsigned*)&As[ab + 8*SA];
                unsigned a2 = *(const unsigned*)&As[ab + 8];
                unsigned a3 = *(const unsigned*)&As[ab + 8*SA + 8];
                #pragma unroll
                for (int c4 = 0; c4 < 4; c4++){
                    int bb = (c4*8 + g)*Wstr + wbase + kk*16 + 2*t;
                    unsigned b0 = *(const unsigned*)&Wres[bb];
                    unsigned b1 = *(const unsigned*)&Wres[bb + 8];
                    mma_bf16(acc[c4], a0, a1, a2, a3, b0, b1);
                }
            }
        }
        #undef STAGE64
    }

    __syncthreads();
    int r0 = 16*warp + g;
    if (gid == 1){
        #pragma unroll
        for (int c4 = 0; c4 < 4; c4++){
            int col = c4*8 + 2*t;
            sm->un.g.redf[r0*33 + col]       = acc[c4][0];
            sm->un.g.redf[r0*33 + col + 1]   = acc[c4][1];
            sm->un.g.redf[(r0+8)*33 + col]   = acc[c4][2];
            sm->un.g.redf[(r0+8)*33 + col+1] = acc[c4][3];
        }
    }
    __syncthreads();
    if (gid == 0){
        #pragma unroll
        for (int c4 = 0; c4 < 4; c4++){
            int col = c4*8 + 2*t;
            float v00 = acc[c4][0] + sm->un.g.redf[r0*33 + col];
            float v01 = acc[c4][1] + sm->un.g.redf[r0*33 + col + 1];
            float v10 = acc[c4][2] + sm->un.g.redf[(r0+8)*33 + col];
            float v11 = acc[c4][3] + sm->un.g.redf[(r0+8)*33 + col+1];
            int n = n0 + col;
            if (bias){ v00 += bias[n]; v01 += bias[n+1]; v10 += bias[n]; v11 += bias[n+1]; }
            if (act){ v00 = gelu_t(v00); v01 = gelu_t(v01); v10 = gelu_t(v10); v11 = gelu_t(v11); }
            unsigned pv0 = bf2(v00, v01);
            unsigned pv1 = bf2(v10, v11);
            *(unsigned*)&C[(size_t)(m0+r0)*Cstr + n]   = pv0;
            *(unsigned*)&C[(size_t)(m0+r0+8)*Cstr + n] = pv1;
            if (fold){
                *(unsigned*)&sm->un.g.redh[r0*SA + col]     = pv0;
                *(unsigned*)&sm->un.g.redh[(r0+8)*SA + col] = pv1;
            }
        }
    }
    __syncthreads();

    if (fold){
        int w8 = tid >> 5;
        int wm = w8 & 3, wn2 = w8 >> 2;
        float acc2[4][4] = {};
        const __nv_bfloat16* R = sm->un.g.redh;
        #pragma unroll
        for (int kk = 0; kk < 2; kk++){
            int ab = (16*wm + g)*SA + kk*16 + 2*t;
            unsigned a0 = *(const unsigned*)&R[ab];
            unsigned a1 = *(const unsigned*)&R[ab + 8*SA];
            unsigned a2 = *(const unsigned*)&R[ab + 8];
            unsigned a3 = *(const unsigned*)&R[ab + 8*SA + 8];
            #pragma unroll
            for (int c4 = 0; c4 < 4; c4++){
                const __nv_bfloat16* wp =
                    &g_WoutT[(size_t)(32*wn2 + c4*8 + g)*Cc + n0 + kk*16 + 2*t];
                unsigned b0 = *(const unsigned*)wp;
                unsigned b1 = *(const unsigned*)(wp + 8);
                mma_bf16(acc2[c4], a0, a1, a2, a3, b0, b1);
            }
        }
        #pragma unroll
        for (int c4 = 0; c4 < 4; c4++){
            int row = m0 + 16*wm + g;
            int dcol = 32*wn2 + c4*8 + 2*t;
            fold_out[(size_t)row*Dd + dcol]       = acc2[c4][0];
            fold_out[(size_t)row*Dd + dcol + 1]   = acc2[c4][1];
            fold_out[(size_t)(row+8)*Dd + dcol]   = acc2[c4][2];
            fold_out[(size_t)(row+8)*Dd + dcol+1] = acc2[c4][3];
        }
        __syncthreads();
    }
}

// 32x64 tile of pairwise squared distances + histogram (256 threads)
__device__ __forceinline__ void pairwise_tile(const float* __restrict__ x, int i0, int j0,
                                              int* __restrict__ hist, SmAll* sm){
    int tid = threadIdx.x;
    #pragma unroll
    for (int q = 0; q < 2; q++){
        int idx = tid + 256*q;
        int r = idx>>4, c4 = (idx&15)*4;
        if (r < 32){
            float4 v = ldcg4(&x[(i0+r)*Dd + c4]);
            sm->un.p.Xi[(c4+0)*32+r]=v.x; sm->un.p.Xi[(c4+1)*32+r]=v.y;
            sm->un.p.Xi[(c4+2)*32+r]=v.z; sm->un.p.Xi[(c4+3)*32+r]=v.w;
        }
    }
    #pragma unroll
    for (int q = 0; q < 4; q++){
        int idx = tid + 256*q;
        int row = idx>>4, c4 = (idx&15)*4;
        float4 v = ldcg4(&x[(j0+row)*Dd + c4]);
        sm->un.p.Xj[(c4+0)*64+row]=v.x; sm->un.p.Xj[(c4+1)*64+row]=v.y;
        sm->un.p.Xj[(c4+2)*64+row]=v.z; sm->un.p.Xj[(c4+3)*64+row]=v.w;
    }
    __syncthreads();
    int ty = tid>>4, tx = tid&15;
    float acc[2][4] = {};
    #pragma unroll
    for (int k = 0; k < 64; k++){
        float a0 = sm->un.p.Xi[k*32 + ty*2];
        float a1 = sm->un.p.Xi[k*32 + ty*2 + 1];
        float4 b = *(const float4*)&sm->un.p.Xj[k*64 + tx*4];
        float d;
        d=a0-b.x; acc[0][0]+=d*d;  d=a0-b.y; acc[0][1]+=d*d;
        d=a0-b.z; acc[0][2]+=d*d;  d=a0-b.w; acc[0][3]+=d*d;
        d=a1-b.x; acc[1][0]+=d*d;  d=a1-b.y; acc[1][1]+=d*d;
        d=a1-b.z; acc[1][2]+=d*d;  d=a1-b.w; acc[1][3]+=d*d;
    }
    #pragma unroll
    for (int i = 0; i < 2; i++){
        int gi = i0 + ty*2 + i;
        #pragma unroll
        for (int j = 0; j < 4; j++){
            int gj = j0 + tx*4 + j;
            float d2 = acc[i][j];
            g_d2[gi*Bp + gj] = d2;
            float dist = sqrtf(d2 > 0.f ? d2 : 1e-12f);
            int bin = (int)(dist*BIN_SC);
            if (bin > NBINS-1) bin = NBINS-1;
            atomicAdd(&hist[bin], 1);
        }
    }
    __syncthreads();
}

// exact median via warp-shuffle scan + warp-cooperative rank walk
__device__ __forceinline__ float median_local(const int* __restrict__ hist, SmAll* sm){
    int tid = threadIdx.x, lane = tid & 31, warp = tid >> 5;
    const int per = NBINS/TPB;   // 128
    int ssum = 0;
    {
        const int* hp = hist + tid*per;
        #pragma unroll 8
        for (int b = 0; b < per/4; b++){
            int4 v = ldcg4i(hp + b*4);
            ssum += v.x+v.y+v.z+v.w;
        }
    }
    int incl = ssum;
    #pragma unroll
    for (int o = 1; o < 32; o <<= 1){
        int n = __shfl_up_sync(0xffffffffu, incl, o);
        if (lane >= o) incl += n;
    }
    if (lane == 31) sm->un.m.cnt[warp] = incl;
    __syncthreads();
    if (warp == 0 && lane < 8){
        int v = sm->un.m.cnt[lane];
        int sacc = v;
        #pragma unroll
        for (int o = 1; o < 8; o <<= 1){
            int n = __shfl_up_sync(0xffu, sacc, o);
            if (lane >= o) sacc += n;
        }
        sm->un.m.woff[lane] = sacc - v;
    }
    __syncthreads();
    int cur  = sm->un.m.woff[warp] + incl;
    int prev = cur - ssum;
    const int k1 = Bp*Bp/2, k2 = Bp*Bp/2 + 1;
    #pragma unroll
    for (int q = 0; q < 2; q++){
        int kq = (q == 0) ? k1 : k2;
        unsigned msk = __ballot_sync(0xffffffffu, prev < kq && kq <= cur);
        if (msk){
            int src   = __ffs(msk) - 1;
            int pbase = __shfl_sync(0xffffffffu, prev, src);
            int cbase = (__shfl_sync(0xffffffffu, tid, src))*per;
            int4 v = ldcg4i(hist + cbase + lane*4);
            int sl = v.x+v.y+v.z+v.w;
            int i2 = sl;
            #pragma unroll
            for (int o = 1; o < 32; o <<= 1){
                int n = __shfl_up_sync(0xffffffffu, i2, o);
                if (lane >= o) i2 += n;
            }
            int cumL = pbase + i2, prevL = cumL - sl;
            if (prevL < kq && kq <= cumL){
                int b = cbase + lane*4, c = prevL, bb;
                c += v.x; if (c >= kq) bb = b;
                else { c += v.y; if (c >= kq) bb = b+1;
                       else { c += v.z; if (c >= kq) bb = b+2; else bb = b+3; } }
                sm->un.m.v[q] = ((float)bb + 0.5f)/BIN_SC;
            }
        }
    }
    __syncthreads();
    float med = 0.5f*(sm->un.m.v[0] + sm->un.m.v[1]);
    float ht = med*med / logf((float)Bp);
    __syncthreads();
    return ht;
}

__global__ void __launch_bounds__(TPB, 1)
cmcd_fused(const float* __restrict__ particles, const float* __restrict__ noises,
           const float* __restrict__ grid_t, const float* __restrict__ eps,
           const float* __restrict__ means, const float* __restrict__ phase,
           const float* __restrict__ in_W, const float* __restrict__ in_b,
           const float* __restrict__ t_W1, const float* __restrict__ t_b1,
           const float* __restrict__ t_W2, const float* __restrict__ t_b2,
           const float* __restrict__ h_W, const float* __restrict__ h_b,
           const float* __restrict__ out_W, const float* __restrict__ out_b,
           float* __restrict__ out)
{
    extern __shared__ unsigned char smem_raw[];
    SmAll* sm = reinterpret_cast<SmAll*>(smem_raw);
    int blk = blockIdx.x, tid = threadIdx.x;
    int gtid = blk*TPB + tid;
    const int NT = GRID*TPB;

    unsigned long long ebase = ld_acq(&g_epoch);
    unsigned long long ecnt = 0;

    int m0 = (blk >> 4) * 64;
    int n0 = (blk & 15) * 32;

    // ── S0: copy slice 0, zero hists, temb, betas, transposed bf16 weights ──
    for (int idx = gtid; idx < Bp*Dd; idx += NT) out[idx] = particles[idx];
    for (int idx = gtid; idx < 2*NBINS; idx += NT) g_hist[0][idx] = 0;
    for (int idx = gtid; idx < Cc*Dd; idx += NT){
        int n = idx & 511, k = idx >> 9;
        g_WinT[n*Dd + k] = __float2bfloat16(in_W[k*Cc + n]);
    }
    for (int idx = gtid; idx < 3*Cc*Cc; idx += NT){
        int l = idx >> 18, r = idx & 262143;
        int n = r & 511, k = r >> 9;
        g_WhT[l*262144 + n*Cc + k] = __float2bfloat16(h_W[l*262144 + k*Cc + n]);
    }
    for (int idx = gtid; idx < Cc*Dd; idx += NT){
        int d = idx & 63, k = idx >> 6;
        g_WoutT[d*Cc + k] = __float2bfloat16(out_W[k*Dd + d]);
    }
    for (int idx = gtid; idx < NBs*2*Cc; idx += NT){
        int s = idx >> 10, c = idx & 1023;
        float t = (float)s;
        int cc = (c < Cc) ? c : c - Cc;
        float coeff = 0.1f + (float)cc*(99.9f/511.0f);
        float e = coeff*t + phase[cc];
        g_temb[idx] = (c < Cc) ? sinf(e) : cosf(e);
    }
    if (gtid == 0){
        float cum = 0.f;
        g_betas[0] = 0.f;
        for (int j = 0; j < NBs; j++){
            float sg = 1.f/(1.f+expf(-grid_t[j]));
            cum += sg;
            g_betas[j+1] = cum;
        }
        float inv = 1.f/cum;
        for (int j = 1; j <= NBs; j++) g_betas[j] *= inv;
    }
    GB();

    // load this block's W tiles into resident smem (constant for all steps)
    for (int l = 0; l < 3; l++)
        for (int idx = tid; idx < 32*Cc; idx += TPB){
            int n = idx >> 9, k = idx & 511;
            sm->Wh[l][n*SW + k] = g_WhT[(size_t)l*Cc*Cc + (size_t)(n0+n)*Cc + k];
        }
    for (int idx = tid; idx < 32*64; idx += TPB){
        int n = idx >> 6, k = idx & 63;
        sm->Win[n*SA + k] = g_WinT[(n0+n)*Dd + k];
    }

    // ── S1: t-MLP layer 1 (8-way K-split + shuffle reduce) ──
    {
        int oidx = gtid >> 3;
        int sl   = gtid & 7;
        int s = oidx >> 9, c = oidx & 511;
        float acc = 0.f;
        const float* tb = g_temb + s*2*Cc;
        int kb = sl*128;
        #pragma unroll 4
        for (int k = kb; k < kb+128; k++) acc += tb[k]*t_W1[k*Cc + c];
        #pragma unroll
        for (int o = 1; o < 8; o <<= 1) acc += __shfl_xor_sync(0xffffffffu, acc, o);
        if (sl == 0) g_tg1[oidx] = gelu_t(acc + t_b1[c]);
    }
    GB();

    // ── S2: t-MLP layer 2 + in_b → fused input bias ──
    {
        int oidx = gtid >> 3;
        int sl   = gtid & 7;
        int s = oidx >> 9, c = oidx & 511;
        float acc = 0.f;
        const float* gb = g_tg1 + s*Cc;
        int kb = sl*64;
        #pragma unroll 4
        for (int k = kb; k < kb+64; k++) acc += gb[k]*t_W2[k*Cc + c];
        #pragma unroll
        for (int o = 1; o < 8; o <<= 1) acc += __shfl_xor_sync(0xffffffffu, acc, o);
        if (sl == 0) g_bias1[oidx] = acc + t_b2[c] + in_b[c];
    }
    GB();

    float* fold_out = g_osp + (size_t)(blk & 15)*Bp*Dd;

    for (int s = 0; s < NBs; s++){
        const float* x = out + (size_t)s*Bp*Dd;
        float* xn      = out + (size_t)(s+1)*Bp*Dd;
        int par = s & 1;

        // ── P1: input layer (K=64, fp32 x converted) + pairwise d2/hist ──
        gemm_bf16(x, Dd, 1, sm->Win, SA, m0, Dd, g_bias1 + s*Cc, n0, 1, 0, nullptr, g_hA, Cc, sm);
        pairwise_tile(x, (blk>>3)*32, (blk&7)*64, g_hist[par], sm);
        GB();

        // ── P2-P4: hidden layers (P4 folds out-layer partials) ──
        gemm_bf16(g_hA, Cc, 0, sm->Wh[0], SW, m0, Cc, h_b + 0*Cc, n0, 1, 0, nullptr, g_hB, Cc, sm);
        GB();
        gemm_bf16(g_hB, Cc, 0, sm->Wh[1], SW, m0, Cc, h_b + 1*Cc, n0, 1, 0, nullptr, g_hA, Cc, sm);
        GB();
        gemm_bf16(g_hA, Cc, 0, sm->Wh[2], SW, m0, Cc, h_b + 2*Cc, n0, 1, 1, fold_out, g_hB, Cc, sm);
        GB();

        // ── P6: median + tensorized repulsion + update ──
        {
            float ht = median_local(g_hist[par], sm);
            float inv_ht = 1.f/ht;
            int lane = tid & 31;
            int p = tid >> 6;
            int d = tid & 63;
            int i = blk*4 + p;

            for (int it = tid; it < 8192; it += TPB){
                int j = it >> 4, d4 = (it & 15)*4;
                float4 v = ldcg4(&x[j*Dd + d4]);
                sm->un.u.Xt[(d4+0)*SX + j] = __float2bfloat16(v.x);
                sm->un.u.Xt[(d4+1)*SX + j] = __float2bfloat16(v.y);
                sm->un.u.Xt[(d4+2)*SX + j] = __float2bfloat16(v.z);
                sm->un.u.Xt[(d4+3)*SX + j] = __float2bfloat16(v.w);
            }
            for (int it = tid; it < 12*SX/2; it += TPB)
                ((unsigned*)(sm->un.u.Aw + 4*SX))[it] = 0;
            if (tid < 4) sm->un.u.S[tid] = 0.f;
            __syncthreads();

            float sw = 0.f;
            #pragma unroll
            for (int q = 0; q < 8; q++){
                int j = d + q*64;
                float wv = expf(-ldcg1(&g_d2[i*Bp + j])*inv_ht);
                __nv_bfloat16 wb = __float2bfloat16(wv);
                sm->un.u.Aw[p*SX + j] = wb;
                sw += __bfloat162float(wb);
            }
            #pragma unroll
            for (int o = 16; o >= 1; o >>= 1) sw += __shfl_xor_sync(0xffffffffu, sw, o);
            if (lane == 0) atomicAdd(&sm->un.u.S[p], sw);

            if (d < MC){
                float sacc = 0.f;
                #pragma unroll 4
                for (int k = 0; k < Dd; k++){
                    float df = ldcg1(&x[i*Dd + k]) - means[d*Dd + k];
                    sacc += df*df;
                }
                float cm = -0.5f*sacc;
                float mx = cm;
                #pragma unroll
                for (int o = 4; o >= 1; o >>= 1) mx = fmaxf(mx, __shfl_xor_sync(0xffu, mx, o));
                float e = expf(cm - mx);
                float se = e;
                #pragma unroll
                for (int o = 4; o >= 1; o >>= 1) se += __shfl_xor_sync(0xffu, se, o);
                sm->un.u.wm[p][d] = e/se;
            }
            __syncthreads();

            {
                int w8 = tid >> 5;
                int g2 = lane >> 2, t2 = lane & 3;
                float accA[4] = {}, accB[4] = {};
                const __nv_bfloat16* Aw = sm->un.u.Aw;
                const __nv_bfloat16* Xt = sm->un.u.Xt + (size_t)(w8*8 + g2)*SX;
                #pragma unroll 8
                for (int kk = 0; kk < 32; kk++){
                    int kb = kk*16 + 2*t2;
                    unsigned a0 = *(const unsigned*)&Aw[g2*SX + kb];
                    unsigned a1 = *(const unsigned*)&Aw[(g2+8)*SX + kb];
                    unsigned a2 = *(const unsigned*)&Aw[g2*SX + kb + 8];
                    unsigned a3 = *(const unsigned*)&Aw[(g2+8)*SX + kb + 8];
                    unsigned b0 = *(const unsigned*)&Xt[kb];
                    unsigned b1 = *(const unsigned*)&Xt[kb + 8];
                    mma_bf16((kk & 1) ? accB : accA, a0, a1, a2, a3, b0, b1);
                }
                if (g2 < 4){
                    sm->un.u.T[g2*64 + w8*8 + 2*t2]     = accA[0] + accB[0];
                    sm->un.u.T[g2*64 + w8*8 + 2*t2 + 1] = accA[1] + accB[1];
                }
            }
            __syncthreads();

            float dt = eps[0];
            float t = g_betas[s];
            float s2dt = sqrtf(2.f*dt);
            float xi_d = ldcg1(&x[i*Dd + d]);
            float Sp = sm->un.u.S[p];
            float Tv = sm->un.u.T[p*64 + d];
            float r = xi_d*Sp - Tv;
            float wbar = 0.f;
            #pragma unroll
            for (int m = 0; m < MC; m++) wbar += sm->un.u.wm[p][m]*means[m*Dd + d];
            float sc = out_b[d];
            #pragma unroll
            for (int nt = 0; nt < 16; nt++)
                sc += ldcg1(&g_osp[((size_t)nt*Bp + i)*Dd + d]);
            float drift = t*wbar - xi_d - sc;
            float nv = noises[((size_t)s*Bp + i)*Dd + d];
            xn[i*Dd + d] = xi_d + dt*drift + s2dt*nv + 0.1f*dt*inv_ht*r;
            for (int idx = gtid; idx < NBINS; idx += NT) g_hist[par^1][idx] = 0;
        }
        GB();
    }
}

extern "C" void kernel_launch(void* const* d_in, const int* in_sizes, int n_in,
                              void* d_out, int out_size){
    const float* particles = (const float*)d_in[0];
    const float* noises    = (const float*)d_in[1];
    const float* grid_t    = (const float*)d_in[2];
    const float* eps       = (const float*)d_in[3];
    const float* means     = (const float*)d_in[4];
    const float* phase     = (const float*)d_in[5];
    const float* in_W      = (const float*)d_in[6];
    const float* in_b      = (const float*)d_in[7];
    const float* t_W1      = (const float*)d_in[8];
    const float* t_b1      = (const float*)d_in[9];
    const float* t_W2      = (const float*)d_in[10];
    const float* t_b2      = (const float*)d_in[11];
    const float* h_W       = (const float*)d_in[12];
    const float* h_b       = (const float*)d_in[13];
    const float* out_W     = (const float*)d_in[14];
    const float* out_b     = (const float*)d_in[15];
    float* out = (float*)d_out;

    static int smem_set = -1;
    int smem_bytes = (int)sizeof(SmAll);
    if (smem_set < 0){
        cudaFuncSetAttribute(cmcd_fused, cudaFuncAttributeMaxDynamicSharedMemorySize, smem_bytes);
        smem_set = 1;
    }

    cmcd_fused<<<GRID, TPB, smem_bytes>>>(particles, noises, grid_t, eps, means, phase,
                                          in_W, in_b, t_W1, t_b1, t_W2, t_b2,
                                          h_W, h_b, out_W, out_b, out);
}

// round 17
// speedup vs baseline: 1.1603x; 1.1603x over previous
#include <cuda_runtime.h>
#include <cuda_bf16.h>
#include <math.h>

#define GRID 128
#define TPB  256
#define Bp   512
#define Dd   64
#define Cc   512
#define NBs  8
#define MC   8
#define NBINS 32768
#define BIN_SC ((float)NBINS/64.0f)
#define BPAD 16

__device__ __nv_bfloat16 g_hA[Bp*Cc];
__device__ __nv_bfloat16 g_hB[Bp*Cc];
__device__ float g_osp[16*Bp*Dd];     // out-layer partials per n-tile
__device__ float g_d2[Bp*Bp];
__device__ float g_temb[NBs*2*Cc];
__device__ float g_tg1[NBs*Cc];
__device__ float g_bias1[NBs*Cc];
__device__ float g_betas[NBs+1];
__device__ __align__(16) int g_hist[2][NBINS];
__device__ unsigned long long g_flags[GRID*BPAD];
// weights transposed to [n][k] and converted to bf16 at setup
__device__ __nv_bfloat16 g_WinT[Cc*Dd];      // [n=Cc][k=Dd]
__device__ __nv_bfloat16 g_WhT[3*Cc*Cc];     // [l][n][k]
__device__ __nv_bfloat16 g_WoutT[Dd*Cc];     // [d][k]

#define SA 72    // smem half-stride for 64-half chunks (conflict-free frags)
#define SX 520   // P6 X/A stride

struct SmG {
    __nv_bfloat16 A[2][3][64*SA];   // [gid][stage]
    __nv_bfloat16 W[2][3][32*SA];
    float redf[64*33];
    __nv_bfloat16 redh[64*SA];
};
struct SmP { float Xi[32*64]; float Xj[64*64]; };
struct SmU {
    __nv_bfloat16 Xt[64*SX];
    __nv_bfloat16 Aw[16*SX];
    float T[4*64];
    float S[4];
    float wm[4][MC];
};
struct SmM { int cnt[8]; int woff[8]; float v[2]; };
union Smem { SmG g; SmP p; SmU u; SmM m; };

__device__ __forceinline__ float gelu_t(float x){
    float x3 = x*x*x;
    return 0.5f*x*(1.0f+tanhf(0.7978845608028654f*(x+0.044715f*x3)));
}

__device__ __forceinline__ unsigned bf2(float lo, float hi){
    unsigned r;
    asm("cvt.rn.bf16x2.f32 %0, %1, %2;" : "=r"(r) : "f"(hi), "f"(lo));
    return r;
}

__device__ __forceinline__ void mma_bf16(float* acc,
    unsigned a0, unsigned a1, unsigned a2, unsigned a3,
    unsigned b0, unsigned b1)
{
    asm volatile(
        "mma.sync.aligned.m16n8k16.row.col.f32.bf16.bf16.f32 "
        "{%0,%1,%2,%3}, {%4,%5,%6,%7}, {%8,%9}, {%0,%1,%2,%3};"
        : "+f"(acc[0]), "+f"(acc[1]), "+f"(acc[2]), "+f"(acc[3])
        : "r"(a0), "r"(a1), "r"(a2), "r"(a3), "r"(b0), "r"(b1));
}

__device__ __forceinline__ void cpa16(void* s, const void* g){
    unsigned sa = (unsigned)__cvta_generic_to_shared(s);
    asm volatile("cp.async.cg.shared.global [%0], [%1], 16;" :: "r"(sa), "l"(g));
}
#define CPA_COMMIT() asm volatile("cp.async.commit_group;" ::: "memory")

// L2-direct loads (bypass L1) for cross-phase re-read data
__device__ __forceinline__ float4 ldcg4(const float* p){
    float4 v;
    asm volatile("ld.global.cg.v4.f32 {%0,%1,%2,%3}, [%4];"
                 : "=f"(v.x),"=f"(v.y),"=f"(v.z),"=f"(v.w) : "l"(p));
    return v;
}
__device__ __forceinline__ float ldcg1(const float* p){
    float v;
    asm volatile("ld.global.cg.f32 %0, [%1];" : "=f"(v) : "l"(p));
    return v;
}
__device__ __forceinline__ int4 ldcg4i(const int* p){
    int4 v;
    asm volatile("ld.global.cg.v4.s32 {%0,%1,%2,%3}, [%4];"
                 : "=r"(v.x),"=r"(v.y),"=r"(v.z),"=r"(v.w) : "l"(p));
    return v;
}

__device__ __forceinline__ unsigned long long ld_acq(const unsigned long long* p){
    unsigned long long v;
    asm volatile("ld.acquire.gpu.global.u64 %0, [%1];" : "=l"(v) : "l"(p) : "memory");
    return v;
}
__device__ __forceinline__ void st_rel(unsigned long long* p, unsigned long long v){
    asm volatile("st.release.gpu.global.u64 [%0], %1;" :: "l"(p), "l"(v) : "memory");
}

// monotone flag protocol: one counter per block, group waits check 16 flags,
// global waits check all 128. No fences, no atomics, no L1 flush.
__device__ __forceinline__ void flag_store(int blk, int tid, unsigned long long v){
    __syncthreads();
    if (tid == 0) st_rel(&g_flags[blk*BPAD], v);
}
__device__ __forceinline__ void wait_group(int grp, int tid, unsigned long long v){
    if (tid < 16){
        const unsigned long long* f = &g_flags[(grp*16 + tid)*BPAD];
        while (ld_acq(f) < v) { }
    }
    __syncthreads();
}
__device__ __forceinline__ void wait_all(int tid, unsigned long long v){
    if (tid < GRID){
        const unsigned long long* f = &g_flags[tid*BPAD];
        while (ld_acq(f) < v) { }
    }
    __syncthreads();
}

// one 64x32 output tile of C = act(A@W + bias) via bf16 tensor cores.
// 256 threads, 2-way K-split. WT is [n][k] bf16. C stored bf16.
// K=512: cp.async 3-stage ring, 64-half chunks. K=64 (convA): register conv.
__device__ __forceinline__ void gemm_bf16(
    const void* Aptr, int Astr, int convA,
    const __nv_bfloat16* __restrict__ WT, int Wstr,
    int m0, int n0, int klen,
    const float* __restrict__ bias, int act,
    int fold, float* __restrict__ fold_out,
    __nv_bfloat16* __restrict__ C, int Cstr, Smem* sm)
{
    int tid  = threadIdx.x;
    int gid  = tid >> 7;
    int tg   = tid & 127;
    int warp = tg >> 5, lane = tid & 31;
    int g = lane >> 2, t = lane & 3;

    float acc[4][4] = {};

    if (convA){
        // single 32-half chunk per gid (P1: fp32 x converted to bf16)
        int kb0 = gid*32;
        int arow = tg >> 1, kseg = (tg & 1)*16;
        int wn   = tg >> 2, kofs = (tg & 3)*8;
        const float* Af = (const float*)Aptr;
        const float* ap = &Af[(size_t)(m0+arow)*Astr + kb0 + kseg];
        float4 f0 = ldcg4(ap),   f1 = ldcg4(ap+4);
        float4 f2 = ldcg4(ap+8), f3 = ldcg4(ap+12);
        uint4 ua, ub;
        ua.x = bf2(f0.x,f0.y); ua.y = bf2(f0.z,f0.w);
        ua.z = bf2(f1.x,f1.y); ua.w = bf2(f1.z,f1.w);
        ub.x = bf2(f2.x,f2.y); ub.y = bf2(f2.z,f2.w);
        ub.z = bf2(f3.x,f3.y); ub.w = bf2(f3.z,f3.w);
        uint4 uw = *(const uint4*)&WT[(size_t)(n0+wn)*Wstr + kb0 + kofs];
        __nv_bfloat16* As = sm->g.A[gid][0];
        __nv_bfloat16* Ws = sm->g.W[gid][0];
        *(uint4*)&As[arow*SA + kseg]     = ua;
        *(uint4*)&As[arow*SA + kseg + 8] = ub;
        *(uint4*)&Ws[wn*SA + kofs]       = uw;
        __syncthreads();
        #pragma unroll
        for (int kk = 0; kk < 2; kk++){
            int ab = (16*warp + g)*SA + kk*16 + 2*t;
            unsigned a0 = *(const unsigned*)&As[ab];
            unsigned a1 = *(const unsigned*)&As[ab + 8*SA];
            unsigned a2 = *(const unsigned*)&As[ab + 8];
            unsigned a3 = *(const unsigned*)&As[ab + 8*SA + 8];
            #pragma unroll
            for (int c4 = 0; c4 < 4; c4++){
                int bb = (c4*8 + g)*SA + kk*16 + 2*t;
                unsigned b0 = *(const unsigned*)&Ws[bb];
                unsigned b1 = *(const unsigned*)&Ws[bb + 8];
                mma_bf16(acc[c4], a0, a1, a2, a3, b0, b1);
            }
        }
    } else {
        // K=512: 4 chunks of 64 halves per gid, 3-stage cp.async ring
        const __nv_bfloat16* Ah = (const __nv_bfloat16*)Aptr;
        int kb0 = gid*256;
        #define STAGE64(chunk, st) do {                                           \
            int kb_ = kb0 + (chunk)*64;                                           \
            __nv_bfloat16* As_ = sm->g.A[gid][st];                                \
            __nv_bfloat16* Ws_ = sm->g.W[gid][st];                                \
            _Pragma("unroll")                                                     \
            for (int q = 0; q < 4; q++){                                          \
                int u = tg + q*128;                                               \
                cpa16(&As_[(u>>3)*SA + (u&7)*8],                                  \
                      &Ah[(size_t)(m0+(u>>3))*Astr + kb_ + (u&7)*8]);             \
            }                                                                     \
            _Pragma("unroll")                                                     \
            for (int q = 0; q < 2; q++){                                          \
                int u = tg + q*128;                                               \
                cpa16(&Ws_[(u>>3)*SA + (u&7)*8],                                  \
                      &WT[(size_t)(n0+(u>>3))*Wstr + kb_ + (u&7)*8]);             \
            }                                                                     \
            CPA_COMMIT();                                                         \
        } while(0)

        STAGE64(0, 0);
        STAGE64(1, 1);
        #pragma unroll
        for (int c = 0; c < 4; c++){
            if (c < 3) asm volatile("cp.async.wait_group 1;" ::: "memory");
            else       asm volatile("cp.async.wait_group 0;" ::: "memory");
            __syncthreads();
            if (c+2 < 4) STAGE64(c+2, (c+2)%3);
            const __nv_bfloat16* As = sm->g.A[gid][c%3];
            const __nv_bfloat16* Ws = sm->g.W[gid][c%3];
            #pragma unroll
            for (int kk = 0; kk < 4; kk++){
                int ab = (16*warp + g)*SA + kk*16 + 2*t;
                unsigned a0 = *(const unsigned*)&As[ab];
                unsigned a1 = *(const unsigned*)&As[ab + 8*SA];
                unsigned a2 = *(const unsigned*)&As[ab + 8];
                unsigned a3 = *(const unsigned*)&As[ab + 8*SA + 8];
                #pragma unroll
                for (int c4 = 0; c4 < 4; c4++){
                    int bb = (c4*8 + g)*SA + kk*16 + 2*t;
                    unsigned b0 = *(const unsigned*)&Ws[bb];
                    unsigned b1 = *(const unsigned*)&Ws[bb + 8];
                    mma_bf16(acc[c4], a0, a1, a2, a3, b0, b1);
                }
            }
        }
        #undef STAGE64
    }

    __syncthreads();
    int r0 = 16*warp + g;
    if (gid == 1){
        #pragma unroll
        for (int c4 = 0; c4 < 4; c4++){
            int col = c4*8 + 2*t;
            sm->g.redf[r0*33 + col]       = acc[c4][0];
            sm->g.redf[r0*33 + col + 1]   = acc[c4][1];
            sm->g.redf[(r0+8)*33 + col]   = acc[c4][2];
            sm->g.redf[(r0+8)*33 + col+1] = acc[c4][3];
        }
    }
    __syncthreads();
    if (gid == 0){
        #pragma unroll
        for (int c4 = 0; c4 < 4; c4++){
            int col = c4*8 + 2*t;
            float v00 = acc[c4][0] + sm->g.redf[r0*33 + col];
            float v01 = acc[c4][1] + sm->g.redf[r0*33 + col + 1];
            float v10 = acc[c4][2] + sm->g.redf[(r0+8)*33 + col];
            float v11 = acc[c4][3] + sm->g.redf[(r0+8)*33 + col+1];
            int n = n0 + col;
            if (bias){ v00 += bias[n]; v01 += bias[n+1]; v10 += bias[n]; v11 += bias[n+1]; }
            if (act){ v00 = gelu_t(v00); v01 = gelu_t(v01); v10 = gelu_t(v10); v11 = gelu_t(v11); }
            unsigned pv0 = bf2(v00, v01);
            unsigned pv1 = bf2(v10, v11);
            *(unsigned*)&C[(size_t)(m0+r0)*Cstr + n]   = pv0;
            *(unsigned*)&C[(size_t)(m0+r0+8)*Cstr + n] = pv1;
            if (fold){
                *(unsigned*)&sm->g.redh[r0*SA + col]     = pv0;
                *(unsigned*)&sm->g.redh[(r0+8)*SA + col] = pv1;
            }
        }
    }
    __syncthreads();

    if (fold){
        int w8 = tid >> 5;
        int wm = w8 & 3, wn2 = w8 >> 2;
        float acc2[4][4] = {};
        const __nv_bfloat16* R = sm->g.redh;
        #pragma unroll
        for (int kk = 0; kk < 2; kk++){
            int ab = (16*wm + g)*SA + kk*16 + 2*t;
            unsigned a0 = *(const unsigned*)&R[ab];
            unsigned a1 = *(const unsigned*)&R[ab + 8*SA];
            unsigned a2 = *(const unsigned*)&R[ab + 8];
            unsigned a3 = *(const unsigned*)&R[ab + 8*SA + 8];
            #pragma unroll
            for (int c4 = 0; c4 < 4; c4++){
                const __nv_bfloat16* wp =
                    &g_WoutT[(size_t)(32*wn2 + c4*8 + g)*Cc + n0 + kk*16 + 2*t];
                unsigned b0 = *(const unsigned*)wp;
                unsigned b1 = *(const unsigned*)(wp + 8);
                mma_bf16(acc2[c4], a0, a1, a2, a3, b0, b1);
            }
        }
        #pragma unroll
        for (int c4 = 0; c4 < 4; c4++){
            int row = m0 + 16*wm + g;
            int dcol = 32*wn2 + c4*8 + 2*t;
            fold_out[(size_t)row*Dd + dcol]       = acc2[c4][0];
            fold_out[(size_t)row*Dd + dcol + 1]   = acc2[c4][1];
            fold_out[(size_t)(row+8)*Dd + dcol]   = acc2[c4][2];
            fold_out[(size_t)(row+8)*Dd + dcol+1] = acc2[c4][3];
        }
        __syncthreads();
    }
}

// 32x64 tile of pairwise squared distances + histogram (256 threads)
__device__ __forceinline__ void pairwise_tile(const float* __restrict__ x, int i0, int j0,
                                              int* __restrict__ hist, Smem* sm){
    int tid = threadIdx.x;
    #pragma unroll
    for (int q = 0; q < 2; q++){
        int idx = tid + 256*q;
        int r = idx>>4, c4 = (idx&15)*4;
        if (r < 32){
            float4 v = ldcg4(&x[(i0+r)*Dd + c4]);
            sm->p.Xi[(c4+0)*32+r]=v.x; sm->p.Xi[(c4+1)*32+r]=v.y;
            sm->p.Xi[(c4+2)*32+r]=v.z; sm->p.Xi[(c4+3)*32+r]=v.w;
        }
    }
    #pragma unroll
    for (int q = 0; q < 4; q++){
        int idx = tid + 256*q;
        int row = idx>>4, c4 = (idx&15)*4;
        float4 v = ldcg4(&x[(j0+row)*Dd + c4]);
        sm->p.Xj[(c4+0)*64+row]=v.x; sm->p.Xj[(c4+1)*64+row]=v.y;
        sm->p.Xj[(c4+2)*64+row]=v.z; sm->p.Xj[(c4+3)*64+row]=v.w;
    }
    __syncthreads();
    int ty = tid>>4, tx = tid&15;
    float acc[2][4] = {};
    #pragma unroll
    for (int k = 0; k < 64; k++){
        float a0 = sm->p.Xi[k*32 + ty*2];
        float a1 = sm->p.Xi[k*32 + ty*2 + 1];
        float4 b = *(const float4*)&sm->p.Xj[k*64 + tx*4];
        float d;
        d=a0-b.x; acc[0][0]+=d*d;  d=a0-b.y; acc[0][1]+=d*d;
        d=a0-b.z; acc[0][2]+=d*d;  d=a0-b.w; acc[0][3]+=d*d;
        d=a1-b.x; acc[1][0]+=d*d;  d=a1-b.y; acc[1][1]+=d*d;
        d=a1-b.z; acc[1][2]+=d*d;  d=a1-b.w; acc[1][3]+=d*d;
    }
    #pragma unroll
    for (int i = 0; i < 2; i++){
        int gi = i0 + ty*2 + i;
        #pragma unroll
        for (int j = 0; j < 4; j++){
            int gj = j0 + tx*4 + j;
            float d2 = acc[i][j];
            g_d2[gi*Bp + gj] = d2;
            float dist = sqrtf(d2 > 0.f ? d2 : 1e-12f);
            int bin = (int)(dist*BIN_SC);
            if (bin > NBINS-1) bin = NBINS-1;
            atomicAdd(&hist[bin], 1);
        }
    }
    __syncthreads();
}

// exact median via warp-shuffle scan + warp-cooperative rank walk
__device__ __forceinline__ float median_local(const int* __restrict__ hist, Smem* sm){
    int tid = threadIdx.x, lane = tid & 31, warp = tid >> 5;
    const int per = NBINS/TPB;   // 128
    int ssum = 0;
    {
        const int* hp = hist + tid*per;
        #pragma unroll 8
        for (int b = 0; b < per/4; b++){
            int4 v = ldcg4i(hp + b*4);
            ssum += v.x+v.y+v.z+v.w;
        }
    }
    int incl = ssum;
    #pragma unroll
    for (int o = 1; o < 32; o <<= 1){
        int n = __shfl_up_sync(0xffffffffu, incl, o);
        if (lane >= o) incl += n;
    }
    if (lane == 31) sm->m.cnt[warp] = incl;
    __syncthreads();
    if (warp == 0 && lane < 8){
        int v = sm->m.cnt[lane];
        int sacc = v;
        #pragma unroll
        for (int o = 1; o < 8; o <<= 1){
            int n = __shfl_up_sync(0xffu, sacc, o);
            if (lane >= o) sacc += n;
        }
        sm->m.woff[lane] = sacc - v;
    }
    __syncthreads();
    int cur  = sm->m.woff[warp] + incl;
    int prev = cur - ssum;
    const int k1 = Bp*Bp/2, k2 = Bp*Bp/2 + 1;
    #pragma unroll
    for (int q = 0; q < 2; q++){
        int kq = (q == 0) ? k1 : k2;
        unsigned msk = __ballot_sync(0xffffffffu, prev < kq && kq <= cur);
        if (msk){
            int src   = __ffs(msk) - 1;
            int pbase = __shfl_sync(0xffffffffu, prev, src);
            int cbase = (__shfl_sync(0xffffffffu, tid, src))*per;
            int4 v = ldcg4i(hist + cbase + lane*4);
            int sl = v.x+v.y+v.z+v.w;
            int i2 = sl;
            #pragma unroll
            for (int o = 1; o < 32; o <<= 1){
                int n = __shfl_up_sync(0xffffffffu, i2, o);
                if (lane >= o) i2 += n;
            }
            int cumL = pbase + i2, prevL = cumL - sl;
            if (prevL < kq && kq <= cumL){
                int b = cbase + lane*4, c = prevL, bb;
                c += v.x; if (c >= kq) bb = b;
                else { c += v.y; if (c >= kq) bb = b+1;
                       else { c += v.z; if (c >= kq) bb = b+2; else bb = b+3; } }
                sm->m.v[q] = ((float)bb + 0.5f)/BIN_SC;
            }
        }
    }
    __syncthreads();
    float med = 0.5f*(sm->m.v[0] + sm->m.v[1]);
    float ht = med*med / logf((float)Bp);
    __syncthreads();
    return ht;
}

__global__ void __launch_bounds__(TPB, 1)
cmcd_fused(const float* __restrict__ particles, const float* __restrict__ noises,
           const float* __restrict__ grid_t, const float* __restrict__ eps,
           const float* __restrict__ means, const float* __restrict__ phase,
           const float* __restrict__ in_W, const float* __restrict__ in_b,
           const float* __restrict__ t_W1, const float* __restrict__ t_b1,
           const float* __restrict__ t_W2, const float* __restrict__ t_b2,
           const float* __restrict__ h_W, const float* __restrict__ h_b,
           const float* __restrict__ out_W, const float* __restrict__ out_b,
           float* __restrict__ out)
{
    extern __shared__ unsigned char smem_raw[];
    Smem* sm = reinterpret_cast<Smem*>(smem_raw);
    int blk = blockIdx.x, tid = threadIdx.x;
    int gtid = blk*TPB + tid;
    const int NT = GRID*TPB;
    int grp = blk >> 4;

    unsigned long long base = ld_acq(&g_flags[blk*BPAD]);
    unsigned long long cnt = 0;

    // ── S0: copy slice 0, zero hists, temb, betas, transposed bf16 weights ──
    for (int idx = gtid; idx < Bp*Dd; idx += NT) out[idx] = particles[idx];
    for (int idx = gtid; idx < 2*NBINS; idx += NT) g_hist[0][idx] = 0;
    for (int idx = gtid; idx < Cc*Dd; idx += NT){
        int n = idx & 511, k = idx >> 9;
        g_WinT[n*Dd + k] = __float2bfloat16(in_W[k*Cc + n]);
    }
    for (int idx = gtid; idx < 3*Cc*Cc; idx += NT){
        int l = idx >> 18, r = idx & 262143;
        int n = r & 511, k = r >> 9;
        g_WhT[l*262144 + n*Cc + k] = __float2bfloat16(h_W[l*262144 + k*Cc + n]);
    }
    for (int idx = gtid; idx < Cc*Dd; idx += NT){
        int d = idx & 63, k = idx >> 6;
        g_WoutT[d*Cc + k] = __float2bfloat16(out_W[k*Dd + d]);
    }
    for (int idx = gtid; idx < NBs*2*Cc; idx += NT){
        int s = idx >> 10, c = idx & 1023;
        float t = (float)s;
        int cc = (c < Cc) ? c : c - Cc;
        float coeff = 0.1f + (float)cc*(99.9f/511.0f);
        float e = coeff*t + phase[cc];
        g_temb[idx] = (c < Cc) ? sinf(e) : cosf(e);
    }
    if (gtid == 0){
        float cum = 0.f;
        g_betas[0] = 0.f;
        for (int j = 0; j < NBs; j++){
            float sg = 1.f/(1.f+expf(-grid_t[j]));
            cum += sg;
            g_betas[j+1] = cum;
        }
        float inv = 1.f/cum;
        for (int j = 1; j <= NBs; j++) g_betas[j] *= inv;
    }
    cnt++; flag_store(blk, tid, base+cnt); wait_all(tid, base+cnt);

    // ── S1: t-MLP layer 1 (8-way K-split + shuffle reduce) ──
    {
        int oidx = gtid >> 3;
        int sl   = gtid & 7;
        int s = oidx >> 9, c = oidx & 511;
        float acc = 0.f;
        const float* tb = g_temb + s*2*Cc;
        int kb = sl*128;
        #pragma unroll 4
        for (int k = kb; k < kb+128; k++) acc += tb[k]*t_W1[k*Cc + c];
        #pragma unroll
        for (int o = 1; o < 8; o <<= 1) acc += __shfl_xor_sync(0xffffffffu, acc, o);
        if (sl == 0) g_tg1[oidx] = gelu_t(acc + t_b1[c]);
    }
    cnt++; flag_store(blk, tid, base+cnt); wait_all(tid, base+cnt);

    // ── S2: t-MLP layer 2 + in_b → fused input bias ──
    {
        int oidx = gtid >> 3;
        int sl   = gtid & 7;
        int s = oidx >> 9, c = oidx & 511;
        float acc = 0.f;
        const float* gb = g_tg1 + s*Cc;
        int kb = sl*64;
        #pragma unroll 4
        for (int k = kb; k < kb+64; k++) acc += gb[k]*t_W2[k*Cc + c];
        #pragma unroll
        for (int o = 1; o < 8; o <<= 1) acc += __shfl_xor_sync(0xffffffffu, acc, o);
        if (sl == 0) g_bias1[oidx] = acc + t_b2[c] + in_b[c];
    }
    cnt++; flag_store(blk, tid, base+cnt); wait_all(tid, base+cnt);

    int m0 = (blk >> 4) * 64;
    int n0 = (blk & 15) * 32;
    float* fold_out = g_osp + (size_t)(blk & 15)*Bp*Dd;

    for (int s = 0; s < NBs; s++){
        const float* x = out + (size_t)s*Bp*Dd;
        float* xn      = out + (size_t)(s+1)*Bp*Dd;
        int par = s & 1;

        // ── P1: input layer (K=64, fp32 x converted) + pairwise d2/hist ──
        gemm_bf16(x, Dd, 1, g_WinT, Dd, m0, n0, Dd, g_bias1 + s*Cc, 1, 0, nullptr, g_hA, Cc, sm);
        pairwise_tile(x, (blk>>3)*32, (blk&7)*64, g_hist[par], sm);
        cnt++;
        unsigned long long p1v = base + cnt;
        flag_store(blk, tid, p1v);
        wait_group(grp, tid, p1v);

        // ── P2-P4: hidden layers (group-local sync; P4 folds out partials) ──
        gemm_bf16(g_hA, Cc, 0, g_WhT + 0*Cc*Cc, Cc, m0, n0, Cc, h_b + 0*Cc, 1, 0, nullptr, g_hB, Cc, sm);
        cnt++; flag_store(blk, tid, base+cnt); wait_group(grp, tid, base+cnt);
        gemm_bf16(g_hB, Cc, 0, g_WhT + 1*Cc*Cc, Cc, m0, n0, Cc, h_b + 1*Cc, 1, 0, nullptr, g_hA, Cc, sm);
        cnt++; flag_store(blk, tid, base+cnt); wait_group(grp, tid, base+cnt);
        gemm_bf16(g_hA, Cc, 0, g_WhT + 2*Cc*Cc, Cc, m0, n0, Cc, h_b + 2*Cc, 1, 1, fold_out, g_hB, Cc, sm);
        cnt++; flag_store(blk, tid, base+cnt); wait_group(grp, tid, base+cnt);

        // ── P6: gate on ALL blocks' P1 (d2/hist complete), then update ──
        wait_all(tid, p1v);
        {
            float ht = median_local(g_hist[par], sm);
            float inv_ht = 1.f/ht;
            int lane = tid & 31;
            int p = tid >> 6;
            int d = tid & 63;
            int i = blk*4 + p;

            for (int it = tid; it < 8192; it += TPB){
                int j = it >> 4, d4 = (it & 15)*4;
                float4 v = ldcg4(&x[j*Dd + d4]);
                sm->u.Xt[(d4+0)*SX + j] = __float2bfloat16(v.x);
                sm->u.Xt[(d4+1)*SX + j] = __float2bfloat16(v.y);
                sm->u.Xt[(d4+2)*SX + j] = __float2bfloat16(v.z);
                sm->u.Xt[(d4+3)*SX + j] = __float2bfloat16(v.w);
            }
            for (int it = tid; it < 12*SX/2; it += TPB)
                ((unsigned*)(sm->u.Aw + 4*SX))[it] = 0;
            if (tid < 4) sm->u.S[tid] = 0.f;
            __syncthreads();

            float sw = 0.f;
            #pragma unroll
            for (int q = 0; q < 8; q++){
                int j = d + q*64;
                float wv = expf(-ldcg1(&g_d2[i*Bp + j])*inv_ht);
                __nv_bfloat16 wb = __float2bfloat16(wv);
                sm->u.Aw[p*SX + j] = wb;
                sw += __bfloat162float(wb);
            }
            #pragma unroll
            for (int o = 16; o >= 1; o >>= 1) sw += __shfl_xor_sync(0xffffffffu, sw, o);
            if (lane == 0) atomicAdd(&sm->u.S[p], sw);

            if (d < MC){
                float sacc = 0.f;
                #pragma unroll 4
                for (int k = 0; k < Dd; k++){
                    float df = ldcg1(&x[i*Dd + k]) - means[d*Dd + k];
                    sacc += df*df;
                }
                float cm = -0.5f*sacc;
                float mx = cm;
                #pragma unroll
                for (int o = 4; o >= 1; o >>= 1) mx = fmaxf(mx, __shfl_xor_sync(0xffu, mx, o));
                float e = expf(cm - mx);
                float se = e;
                #pragma unroll
                for (int o = 4; o >= 1; o >>= 1) se += __shfl_xor_sync(0xffu, se, o);
                sm->u.wm[p][d] = e/se;
            }
            __syncthreads();

            {
                int w8 = tid >> 5;
                int g2 = lane >> 2, t2 = lane & 3;
                float accA[4] = {}, accB[4] = {};
                const __nv_bfloat16* Aw = sm->u.Aw;
                const __nv_bfloat16* Xt = sm->u.Xt + (size_t)(w8*8 + g2)*SX;
                #pragma unroll 8
                for (int kk = 0; kk < 32; kk++){
                    int kb = kk*16 + 2*t2;
                    unsigned a0 = *(const unsigned*)&Aw[g2*SX + kb];
                    unsigned a1 = *(const unsigned*)&Aw[(g2+8)*SX + kb];
                    unsigned a2 = *(const unsigned*)&Aw[g2*SX + kb + 8];
                    unsigned a3 = *(const unsigned*)&Aw[(g2+8)*SX + kb + 8];
                    unsigned b0 = *(const unsigned*)&Xt[kb];
                    unsigned b1 = *(const unsigned*)&Xt[kb + 8];
                    mma_bf16((kk & 1) ? accB : accA, a0, a1, a2, a3, b0, b1);
                }
                if (g2 < 4){
                    sm->u.T[g2*64 + w8*8 + 2*t2]     = accA[0] + accB[0];
                    sm->u.T[g2*64 + w8*8 + 2*t2 + 1] = accA[1] + accB[1];
                }
            }
            __syncthreads();

            float dt = eps[0];
            float t = g_betas[s];
            float s2dt = sqrtf(2.f*dt);
            float xi_d = ldcg1(&x[i*Dd + d]);
            float Sp = sm->u.S[p];
            float Tv = sm->u.T[p*64 + d];
            float r = xi_d*Sp - Tv;
            float wbar = 0.f;
            #pragma unroll
            for (int m = 0; m < MC; m++) wbar += sm->u.wm[p][m]*means[m*Dd + d];
            float sc = out_b[d];
            #pragma unroll
            for (int nt = 0; nt < 16; nt++)
                sc += ldcg1(&g_osp[((size_t)nt*Bp + i)*Dd + d]);
            float drift = t*wbar - xi_d - sc;
            float nv = noises[((size_t)s*Bp + i)*Dd + d];
            xn[i*Dd + d] = xi_d + dt*drift + s2dt*nv + 0.1f*dt*inv_ht*r;
            for (int idx = gtid; idx < NBINS; idx += NT) g_hist[par^1][idx] = 0;
        }
        // ── end-of-step global barrier: next P1 reads all new particles ──
        cnt++; flag_store(blk, tid, base+cnt); wait_all(tid, base+cnt);
    }
}

extern "C" void kernel_launch(void* const* d_in, const int* in_sizes, int n_in,
                              void* d_out, int out_size){
    const float* particles = (const float*)d_in[0];
    const float* noises    = (const float*)d_in[1];
    const float* grid_t    = (const float*)d_in[2];
    const float* eps       = (const float*)d_in[3];
    const float* means     = (const float*)d_in[4];
    const float* phase     = (const float*)d_in[5];
    const float* in_W      = (const float*)d_in[6];
    const float* in_b      = (const float*)d_in[7];
    const float* t_W1      = (const float*)d_in[8];
    const float* t_b1      = (const float*)d_in[9];
    const float* t_W2      = (const float*)d_in[10];
    const float* t_b2      = (const float*)d_in[11];
    const float* h_W       = (const float*)d_in[12];
    const float* h_b       = (const float*)d_in[13];
    const float* out_W     = (const float*)d_in[14];
    const float* out_b     = (const float*)d_in[15];
    float* out = (float*)d_out;

    static int smem_set = -1;
    int smem_bytes = (int)sizeof(Smem);
    if (smem_set < 0){
        cudaFuncSetAttribute(cmcd_fused, cudaFuncAttributeMaxDynamicSharedMemorySize, smem_bytes);
        smem_set = 1;
    }

    cmcd_fused<<<GRID, TPB, smem_bytes>>>(particles, noises, grid_t, eps, means, phase,
                                          in_W, in_b, t_W1, t_b1, t_W2, t_b2,
                                          h_W, h_b, out_W, out_b, out);
}